// round 4
// baseline (speedup 1.0000x reference)
#include <cuda_runtime.h>
#include <math.h>

#define C_   512
#define RC_  32
#define T_   96
#define HW_  196
#define NB_  2
#define B_   (NB_*T_)   // 192

// ---------------- scratch ----------------
__device__ float g_u[C_];
__device__ float g_mean[B_*C_];
__device__ float g_max[B_*C_];
__device__ float g_m[B_*C_];
__device__ float g_tmp1[B_*C_];
__device__ float g_xatt[B_*C_];
__device__ float g_y[B_*C_];
__device__ float g_z[B_*C_];
__device__ float g_feat[B_*C_];
__device__ float g_d[B_*6*HW_];                 // correlation -> gate (in place)
__device__ float g_xdown[NB_*RC_*T_*HW_];
__device__ float g_aggrc[NB_*RC_*T_*HW_];

// ---------------- zero scratch that is accumulated atomically ----------------
__global__ void k_zero() {
    int i = blockIdx.x * blockDim.x + threadIdx.x;
    if (i < B_*6*HW_) g_d[i] = 0.f;
    if (i < B_*C_)    g_z[i] = 0.f;
}

// ---------------- qp, u = k_w^T qp ----------------
__global__ void k_prep(const float* __restrict__ query, const float* __restrict__ q_w,
                       const float* __restrict__ q_b, const float* __restrict__ k_w) {
    __shared__ float q_s[C_];
    __shared__ float qp_s[C_];
    int tid = threadIdx.x;
    q_s[tid] = query[tid];
    __syncthreads();
    float s = 0.f;
    const float* row = q_w + (size_t)tid * C_;
    for (int c = 0; c < C_; c++) s += q_s[c] * row[c];
    qp_s[tid] = (s + q_b[tid]) * (1.0f / sqrtf((float)C_));
    __syncthreads();
    float u = 0.f;
    for (int cp = 0; cp < C_; cp++) u += qp_s[cp] * k_w[(size_t)cp * C_ + tid];
    g_u[tid] = u;
}

// ---------------- per-(n,t): mean/max over l, softmax(u·x), m = attn-weighted avg ----------------
__global__ void k_stats(const float* __restrict__ x) {
    int b = blockIdx.x;
    int n = b / T_, t = b % T_;
    int tid = threadIdx.x;
    int w = tid >> 5, lane = tid & 31;

    __shared__ float u_s[C_];
    __shared__ float sp[16 * HW_];
    __shared__ float attn[HW_];
    __shared__ float red[2];

    u_s[tid] = g_u[tid];
    for (int i = tid; i < 16 * HW_; i += 512) sp[i] = 0.f;
    __syncthreads();

    const float* xb = x + ((size_t)n * C_ * T_ + t) * HW_;
    for (int ci = 0; ci < 32; ci++) {
        int c = w * 32 + ci;
        const float* row = xb + (size_t)c * T_ * HW_;
        float sm = 0.f, mx = -3.4e38f;
        float uc = u_s[c];
        for (int l = lane; l < HW_; l += 32) {
            float v = row[l];
            sm += v;
            mx = fmaxf(mx, v);
            sp[w * HW_ + l] += uc * v;
        }
        for (int off = 16; off; off >>= 1) {
            sm += __shfl_xor_sync(~0u, sm, off);
            mx = fmaxf(mx, __shfl_xor_sync(~0u, mx, off));
        }
        if (lane == 0) {
            g_mean[b * C_ + c] = sm * (1.f / HW_);
            g_max[b * C_ + c]  = mx;
        }
    }
    __syncthreads();

    if (tid < HW_) {
        float s = 0.f;
        for (int ww = 0; ww < 16; ww++) s += sp[ww * HW_ + tid];
        attn[tid] = s;
    }
    __syncthreads();
    if (w == 0) {
        float mx = -3.4e38f;
        for (int l = lane; l < HW_; l += 32) mx = fmaxf(mx, attn[l]);
        for (int off = 16; off; off >>= 1) mx = fmaxf(mx, __shfl_xor_sync(~0u, mx, off));
        if (lane == 0) red[0] = mx;
    }
    __syncthreads();
    if (tid < HW_) attn[tid] = expf(attn[tid] - red[0]);
    __syncthreads();
    if (w == 0) {
        float s = 0.f;
        for (int l = lane; l < HW_; l += 32) s += attn[l];
        for (int off = 16; off; off >>= 1) s += __shfl_xor_sync(~0u, s, off);
        if (lane == 0) red[1] = s;
    }
    __syncthreads();
    float inv = 1.f / red[1];

    for (int ci = 0; ci < 32; ci++) {
        int c = w * 32 + ci;
        const float* row = xb + (size_t)c * T_ * HW_;
        float acc = 0.f;
        for (int l = lane; l < HW_; l += 32) acc += attn[l] * row[l];
        for (int off = 16; off; off >>= 1) acc += __shfl_xor_sync(~0u, acc, off);
        if (lane == 0) g_m[b * C_ + c] = acc * inv;
    }
}

// ---------------- generic per-b row-dot GEMV: out[b,o] = W[o,:]·vec[b,:] + bias[o] ----------------
__global__ void k_rowdot(const float* __restrict__ W, const float* __restrict__ bias,
                         const float* __restrict__ vecs, float* __restrict__ out) {
    int b = blockIdx.x;
    int tid = threadIdx.x;
    int w = tid >> 5, lane = tid & 31;
    __shared__ float v_s[C_];
    v_s[tid] = vecs[b * C_ + tid];
    __syncthreads();
    for (int oi = 0; oi < 32; oi++) {
        int o = w * 32 + oi;
        const float* row = W + (size_t)o * C_;
        float acc = 0.f;
        for (int c = lane; c < C_; c += 32) acc += row[c] * v_s[c];
        for (int off = 16; off; off >>= 1) acc += __shfl_xor_sync(~0u, acc, off);
        if (lane == 0) out[b * C_ + o] = acc + (bias ? bias[o] : 0.f);
    }
}

// ---------------- xq = w4·(mean,max,xatt);  y = W2^T · xq ----------------
__global__ void k_xq_y(const float* __restrict__ w4, const float* __restrict__ W2) {
    int b = blockIdx.x, tid = threadIdx.x;
    __shared__ float xq[C_];
    xq[tid] = w4[0] * g_mean[b * C_ + tid] + w4[1] * g_max[b * C_ + tid]
            + w4[2] * g_xatt[b * C_ + tid];
    __syncthreads();
    float acc = 0.f;
    for (int o = 0; o < C_; o++) acc += W2[(size_t)o * C_ + tid] * xq[o];
    g_y[b * C_ + tid] = acc;
}

// ---------------- d[n,t,j,l] = sum_c y[n,c,t] * x[n,c,t+off_j,l]  (atomic over c-chunks) ----------------
__global__ void k_d(const float* __restrict__ x) {
    int bid = blockIdx.x;
    int chunk = bid & 3;
    int frame = bid >> 2;
    int n = frame / T_, tp = frame % T_;
    const int offs[6] = {-3, -2, -1, 1, 2, 3};
    __shared__ float y_s[6 * 128];
    int tid = threadIdx.x;
    for (int i = tid; i < 6 * 128; i += blockDim.x) {
        int k = i >> 7, c = i & 127;
        int tk = tp - offs[k];
        y_s[i] = (tk >= 0 && tk < T_) ? g_y[(n * T_ + tk) * C_ + chunk * 128 + c] : 0.f;
    }
    __syncthreads();
    int l = tid;
    if (l < HW_) {
        float acc[6] = {0, 0, 0, 0, 0, 0};
        const float* xb = x + (((size_t)(n * C_ + chunk * 128)) * T_ + tp) * HW_ + l;
        for (int c = 0; c < 128; c++) {
            float v = xb[(size_t)c * T_ * HW_];
#pragma unroll
            for (int k = 0; k < 6; k++) acc[k] += y_s[k * 128 + c] * v;
        }
#pragma unroll
        for (int k = 0; k < 6; k++) {
            int tk = tp - offs[k];
            if (tk >= 0 && tk < T_)
                atomicAdd(&g_d[((n * T_ + tk) * 6 + k) * HW_ + l], acc[k]);
        }
    }
}

// ---------------- gate: g = sigmoid(w2[j]*d) - 0.5  (in place) ----------------
__global__ void k_g(const float* __restrict__ w2) {
    int idx = blockIdx.x * blockDim.x + threadIdx.x;
    if (idx >= B_ * 6 * HW_) return;
    int j = (idx / HW_) % 6;
    float a = w2[j] * g_d[idx];
    g_d[idx] = 1.f / (1.f + expf(-a)) - 0.5f;
}

// ---------------- z[n,c,t] += w2[j] * sum_l x[n,c,t+off_j,l] * g[n,t,j,l] ----------------
__global__ void k_z(const float* __restrict__ x, const float* __restrict__ w2) {
    int bid = blockIdx.x;
    int chunk = bid & 3;
    int frame = bid >> 2;
    int n = frame / T_, tp = frame % T_;
    const int offs[6] = {-3, -2, -1, 1, 2, 3};
    __shared__ float gw[6 * HW_];
    int tid = threadIdx.x;
    for (int i = tid; i < 6 * HW_; i += blockDim.x) {
        int k = i / HW_, l = i % HW_;
        int tk = tp - offs[k];
        gw[i] = (tk >= 0 && tk < T_) ? w2[k] * g_d[((n * T_ + tk) * 6 + k) * HW_ + l] : 0.f;
    }
    __syncthreads();
    int warp = tid >> 5, lane = tid & 31;
    for (int ci = 0; ci < 16; ci++) {
        int c = chunk * 128 + warp * 16 + ci;
        const float* row = x + (((size_t)(n * C_ + c)) * T_ + tp) * HW_;
        float acc[6] = {0, 0, 0, 0, 0, 0};
        for (int l = lane; l < HW_; l += 32) {
            float v = row[l];
#pragma unroll
            for (int k = 0; k < 6; k++) acc[k] += gw[k * HW_ + l] * v;
        }
#pragma unroll
        for (int k = 0; k < 6; k++)
            for (int off = 16; off; off >>= 1) acc[k] += __shfl_xor_sync(~0u, acc[k], off);
        if (lane == 0) {
#pragma unroll
            for (int k = 0; k < 6; k++) {
                int tk = tp - offs[k];
                if (tk >= 0 && tk < T_) atomicAdd(&g_z[(n * T_ + tk) * C_ + c], acc[k]);
            }
        }
    }
}

// ---------------- x_down = down_conv_w · x  (smem-tiled, 2 r per thread) ----------------
#define XCH 32
__global__ void k_xdown(const float* __restrict__ x, const float* __restrict__ dw) {
    int rhalf = blockIdx.x & 1;
    int frame = blockIdx.x >> 1;
    int n = frame / T_, t = frame % T_;
    int tid = threadIdx.x;
    int slot = tid >> 5, lane = tid & 31;
    int r0 = rhalf * 16 + slot * 2;
    __shared__ float xs[XCH * HW_];
    float acc0[7] = {0, 0, 0, 0, 0, 0, 0};
    float acc1[7] = {0, 0, 0, 0, 0, 0, 0};
    for (int c0 = 0; c0 < C_; c0 += XCH) {
        __syncthreads();
        for (int i = tid; i < XCH * HW_; i += 256) {
            int c = i / HW_, l = i % HW_;
            xs[i] = x[(((size_t)(n * C_ + c0 + c)) * T_ + t) * HW_ + l];
        }
        __syncthreads();
        for (int c = 0; c < XCH; c++) {
            float w0 = dw[(size_t)r0 * C_ + c0 + c];
            float w1 = dw[(size_t)(r0 + 1) * C_ + c0 + c];
#pragma unroll
            for (int ll = 0; ll < 7; ll++) {
                int li = lane + 32 * ll;
                if (li < HW_) {
                    float v = xs[c * HW_ + li];
                    acc0[ll] += w0 * v;
                    acc1[ll] += w1 * v;
                }
            }
        }
    }
#pragma unroll
    for (int ll = 0; ll < 7; ll++) {
        int li = lane + 32 * ll;
        if (li < HW_) {
            g_xdown[(((size_t)(n * RC_ + r0)) * T_ + t) * HW_ + li]     = acc0[ll];
            g_xdown[(((size_t)(n * RC_ + r0 + 1)) * T_ + t) * HW_ + li] = acc1[ll];
        }
    }
}

// ---------------- fused 3-branch dilated depthwise conv (t-tiled in smem) ----------------
#define DTILE 8
__global__ void k_dw(const float* __restrict__ sa1w, const float* __restrict__ sa1b,
                     const float* __restrict__ sa2w, const float* __restrict__ sa2b,
                     const float* __restrict__ sa3w, const float* __restrict__ sa3b,
                     const float* __restrict__ wts) {
    int bid = bid = blockIdx.x;
    int ttile = bid % (T_ / DTILE);
    int nr = bid / (T_ / DTILE);
    int r = nr % RC_, n = nr / RC_;
    int tstart = ttile * DTILE;
    __shared__ float xs[(DTILE + 8) * HW_];
    __shared__ float ws[3 * 81];
    __shared__ float bsum_s;
    int tid = threadIdx.x;
    if (tid < 81) {
        ws[tid]       = wts[0] * sa1w[r * 81 + tid];
        ws[81 + tid]  = wts[1] * sa2w[r * 81 + tid];
        ws[162 + tid] = wts[2] * sa3w[r * 81 + tid];
    }
    if (tid == 0) bsum_s = wts[0] * sa1b[r] + wts[1] * sa2b[r] + wts[2] * sa3b[r];
    const float* xdbase = g_xdown + ((size_t)(n * RC_ + r)) * T_ * HW_;
    for (int i = tid; i < (DTILE + 8) * HW_; i += blockDim.x) {
        int row = i / HW_, l = i % HW_;
        int tg = tstart - 4 + row;
        xs[i] = (tg >= 0 && tg < T_) ? xdbase[tg * HW_ + l] : 0.f;
    }
    __syncthreads();
    for (int item = tid; item < DTILE * HW_; item += blockDim.x) {
        int tl = item / HW_, l = item % HW_;
        int h = l / 14, w = l % 14;
        float acc = bsum_s;
#pragma unroll
        for (int d = 1; d <= 3; d++) {
            const float* wb = ws + (d - 1) * 81;
            for (int kt = 0; kt < 9; kt++) {
                const float* xrow = xs + (tl + kt) * HW_;
#pragma unroll
                for (int kh = 0; kh < 3; kh++) {
                    int hh = h + (kh - 1) * d;
                    if (hh < 0 || hh >= 14) continue;
#pragma unroll
                    for (int kw = 0; kw < 3; kw++) {
                        int wp = w + (kw - 1) * d;
                        if (wp < 0 || wp >= 14) continue;
                        acc += wb[kt * 9 + kh * 3 + kw] * xrow[hh * 14 + wp];
                    }
                }
            }
        }
        g_aggrc[(((size_t)(n * RC_ + r)) * T_ + tstart + tl) * HW_ + l] = acc;
    }
}

// ---------------- out = feat * (sigmoid(conv_back · agg_rc) - 0.5) ----------------
__global__ void k_out(const float* __restrict__ cbw, float* __restrict__ out) {
    int b = blockIdx.x;
    int n = b / T_, t = b % T_;
    int tid = threadIdx.x;
    int warp = tid >> 5, lane = tid & 31;
    __shared__ float agg_s[RC_ * HW_];
    __shared__ float feat_s[C_];
    feat_s[tid] = g_feat[b * C_ + tid];
    for (int i = tid; i < RC_ * HW_; i += 512) {
        int r = i / HW_, l = i % HW_;
        agg_s[i] = g_aggrc[(((size_t)(n * RC_ + r)) * T_ + t) * HW_ + l];
    }
    __syncthreads();
    for (int ci = 0; ci < 32; ci++) {
        int c = warp * 32 + ci;
        float wreg[RC_];
#pragma unroll
        for (int r = 0; r < RC_; r++) wreg[r] = cbw[(size_t)c * RC_ + r];
        float fc = feat_s[c];
        float* orow = out + (((size_t)(n * C_ + c)) * T_ + t) * HW_;
        for (int l = lane; l < HW_; l += 32) {
            float a = 0.f;
#pragma unroll
            for (int r = 0; r < RC_; r++) a += wreg[r] * agg_s[r * HW_ + l];
            orow[l] = fc * (1.f / (1.f + expf(-a)) - 0.5f);
        }
    }
}

// ---------------- launcher ----------------
extern "C" void kernel_launch(void* const* d_in, const int* in_sizes, int n_in,
                              void* d_out, int out_size) {
    const float* x     = (const float*)d_in[0];
    const float* W2    = (const float*)d_in[1];   // down_conv2_w (C,C)
    const float* dw    = (const float*)d_in[2];   // down_conv_w  (rc,C)
    const float* cbw   = (const float*)d_in[3];   // conv_back_w  (C,rc)
    const float* w2    = (const float*)d_in[4];   // weights2 (6)
    const float* w4    = (const float*)d_in[5];   // weights4 (3)
    const float* wts   = (const float*)d_in[6];   // weights  (3)
    const float* query = (const float*)d_in[7];
    const float* q_w   = (const float*)d_in[8];
    const float* q_b   = (const float*)d_in[9];
    const float* k_w   = (const float*)d_in[10];
    // d_in[11] = k_b (unused: constant shift, softmax-invariant)
    const float* v_w   = (const float*)d_in[12];
    const float* v_b   = (const float*)d_in[13];
    const float* c_w   = (const float*)d_in[14];
    const float* c_b   = (const float*)d_in[15];
    const float* sa1w  = (const float*)d_in[16];
    const float* sa1b  = (const float*)d_in[17];
    const float* sa2w  = (const float*)d_in[18];
    const float* sa2b  = (const float*)d_in[19];
    const float* sa3w  = (const float*)d_in[20];
    const float* sa3b  = (const float*)d_in[21];
    float* out = (float*)d_out;

    float *p_m, *p_tmp1, *p_xatt, *p_z, *p_feat;
    cudaGetSymbolAddress((void**)&p_m, g_m);
    cudaGetSymbolAddress((void**)&p_tmp1, g_tmp1);
    cudaGetSymbolAddress((void**)&p_xatt, g_xatt);
    cudaGetSymbolAddress((void**)&p_z, g_z);
    cudaGetSymbolAddress((void**)&p_feat, g_feat);

    k_zero<<<(B_*6*HW_ + 255) / 256, 256>>>();
    k_prep<<<1, C_>>>(query, q_w, q_b, k_w);
    k_stats<<<B_, 512>>>(x);
    k_rowdot<<<B_, 512>>>(v_w, v_b, p_m, p_tmp1);       // tmp1 = v_w·m + v_b
    k_rowdot<<<B_, 512>>>(c_w, c_b, p_tmp1, p_xatt);    // xatt = c_w·tmp1 + c_b
    k_xq_y<<<B_, 512>>>(w4, W2);                        // y = W2^T · xq
    k_d<<<B_ * 4, 224>>>(x);                            // correlation
    k_g<<<(B_*6*HW_ + 255) / 256, 256>>>(w2);           // sigmoid gate
    k_z<<<B_ * 4, 256>>>(x, w2);                        // gated aggregation
    k_rowdot<<<B_, 512>>>(W2, nullptr, p_z, p_feat);    // feat = W2 · z
    k_xdown<<<B_ * 2, 256>>>(x, dw);
    k_dw<<<NB_ * RC_ * (T_ / DTILE), 256>>>(sa1w, sa1b, sa2w, sa2b, sa3w, sa3b, wts);
    k_out<<<B_, 512>>>(cbw, out);
}

// round 5
// speedup vs baseline: 1.0076x; 1.0076x over previous
#include <cuda_runtime.h>
#include <math.h>

#define C_   512
#define RC_  32
#define T_   96
#define HW_  196
#define NB_  2
#define B_   (NB_*T_)   // 192

// ---------------- scratch ----------------
__device__ float g_u[C_];
__device__ float g_mean[B_*C_];
__device__ float g_max[B_*C_];
__device__ float g_m[B_*C_];
__device__ float g_tmp1[B_*C_];
__device__ float g_xatt[B_*C_];
__device__ float g_y[B_*C_];
__device__ float g_z[B_*C_];
__device__ float g_feat[B_*C_];
__device__ float g_d[B_*6*HW_];                 // correlation -> gate (in place)
__device__ float g_xdown[NB_*RC_*T_*HW_];
__device__ float g_aggrc[NB_*RC_*T_*HW_];

// ---------------- zero scratch that is accumulated atomically ----------------
__global__ void k_zero() {
    int i = blockIdx.x * blockDim.x + threadIdx.x;
    if (i < B_*6*HW_) g_d[i] = 0.f;
    if (i < B_*C_)    g_z[i] = 0.f;
}

// ---------------- qp, u = k_w^T qp ----------------
__global__ void k_prep(const float* __restrict__ query, const float* __restrict__ q_w,
                       const float* __restrict__ q_b, const float* __restrict__ k_w) {
    __shared__ float q_s[C_];
    __shared__ float qp_s[C_];
    int tid = threadIdx.x;
    q_s[tid] = query[tid];
    __syncthreads();
    float s = 0.f;
    const float* row = q_w + (size_t)tid * C_;
    for (int c = 0; c < C_; c++) s += q_s[c] * row[c];
    qp_s[tid] = (s + q_b[tid]) * (1.0f / sqrtf((float)C_));
    __syncthreads();
    float u = 0.f;
    for (int cp = 0; cp < C_; cp++) u += qp_s[cp] * k_w[(size_t)cp * C_ + tid];
    g_u[tid] = u;
}

// ---------------- per-(n,t): mean/max over l, softmax(u·x), m = attn-weighted avg ----------------
__global__ void k_stats(const float* __restrict__ x) {
    int b = blockIdx.x;
    int n = b / T_, t = b % T_;
    int tid = threadIdx.x;
    int w = tid >> 5, lane = tid & 31;

    __shared__ float u_s[C_];
    __shared__ float sp[16 * HW_];
    __shared__ float attn[HW_];
    __shared__ float red[2];

    u_s[tid] = g_u[tid];
    for (int i = tid; i < 16 * HW_; i += 512) sp[i] = 0.f;
    __syncthreads();

    const float* xb = x + ((size_t)n * C_ * T_ + t) * HW_;
    for (int ci = 0; ci < 32; ci++) {
        int c = w * 32 + ci;
        const float* row = xb + (size_t)c * T_ * HW_;
        float sm = 0.f, mx = -3.4e38f;
        float uc = u_s[c];
        for (int l = lane; l < HW_; l += 32) {
            float v = row[l];
            sm += v;
            mx = fmaxf(mx, v);
            sp[w * HW_ + l] += uc * v;
        }
        for (int off = 16; off; off >>= 1) {
            sm += __shfl_xor_sync(~0u, sm, off);
            mx = fmaxf(mx, __shfl_xor_sync(~0u, mx, off));
        }
        if (lane == 0) {
            g_mean[b * C_ + c] = sm * (1.f / HW_);
            g_max[b * C_ + c]  = mx;
        }
    }
    __syncthreads();

    if (tid < HW_) {
        float s = 0.f;
        for (int ww = 0; ww < 16; ww++) s += sp[ww * HW_ + tid];
        attn[tid] = s;
    }
    __syncthreads();
    if (w == 0) {
        float mx = -3.4e38f;
        for (int l = lane; l < HW_; l += 32) mx = fmaxf(mx, attn[l]);
        for (int off = 16; off; off >>= 1) mx = fmaxf(mx, __shfl_xor_sync(~0u, mx, off));
        if (lane == 0) red[0] = mx;
    }
    __syncthreads();
    if (tid < HW_) attn[tid] = expf(attn[tid] - red[0]);
    __syncthreads();
    if (w == 0) {
        float s = 0.f;
        for (int l = lane; l < HW_; l += 32) s += attn[l];
        for (int off = 16; off; off >>= 1) s += __shfl_xor_sync(~0u, s, off);
        if (lane == 0) red[1] = s;
    }
    __syncthreads();
    float inv = 1.f / red[1];

    for (int ci = 0; ci < 32; ci++) {
        int c = w * 32 + ci;
        const float* row = xb + (size_t)c * T_ * HW_;
        float acc = 0.f;
        for (int l = lane; l < HW_; l += 32) acc += attn[l] * row[l];
        for (int off = 16; off; off >>= 1) acc += __shfl_xor_sync(~0u, acc, off);
        if (lane == 0) g_m[b * C_ + c] = acc * inv;
    }
}

// ---------------- generic per-b row-dot GEMV: out[b,o] = W[o,:]·vec[b,:] + bias[o] ----------------
__global__ void k_rowdot(const float* __restrict__ W, const float* __restrict__ bias,
                         const float* __restrict__ vecs, float* __restrict__ out) {
    int b = blockIdx.x;
    int tid = threadIdx.x;
    int w = tid >> 5, lane = tid & 31;
    __shared__ float v_s[C_];
    v_s[tid] = vecs[b * C_ + tid];
    __syncthreads();
    for (int oi = 0; oi < 32; oi++) {
        int o = w * 32 + oi;
        const float* row = W + (size_t)o * C_;
        float acc = 0.f;
        for (int c = lane; c < C_; c += 32) acc += row[c] * v_s[c];
        for (int off = 16; off; off >>= 1) acc += __shfl_xor_sync(~0u, acc, off);
        if (lane == 0) out[b * C_ + o] = acc + (bias ? bias[o] : 0.f);
    }
}

// ---------------- xq = w4·(mean,max,xatt);  y = W2^T · xq ----------------
__global__ void k_xq_y(const float* __restrict__ w4, const float* __restrict__ W2) {
    int b = blockIdx.x, tid = threadIdx.x;
    __shared__ float xq[C_];
    xq[tid] = w4[0] * g_mean[b * C_ + tid] + w4[1] * g_max[b * C_ + tid]
            + w4[2] * g_xatt[b * C_ + tid];
    __syncthreads();
    float acc = 0.f;
    for (int o = 0; o < C_; o++) acc += W2[(size_t)o * C_ + tid] * xq[o];
    g_y[b * C_ + tid] = acc;
}

// ---------------- d[n,t,j,l] = sum_c y[n,c,t] * x[n,c,t+off_j,l]  (atomic over c-chunks) ----------------
__global__ void k_d(const float* __restrict__ x) {
    int bid = blockIdx.x;
    int chunk = bid & 3;
    int frame = bid >> 2;
    int n = frame / T_, tp = frame % T_;
    const int offs[6] = {-3, -2, -1, 1, 2, 3};
    __shared__ float y_s[6 * 128];
    int tid = threadIdx.x;
    for (int i = tid; i < 6 * 128; i += blockDim.x) {
        int k = i >> 7, c = i & 127;
        int tk = tp - offs[k];
        y_s[i] = (tk >= 0 && tk < T_) ? g_y[(n * T_ + tk) * C_ + chunk * 128 + c] : 0.f;
    }
    __syncthreads();
    int l = tid;
    if (l < HW_) {
        float acc[6] = {0, 0, 0, 0, 0, 0};
        const float* xb = x + (((size_t)(n * C_ + chunk * 128)) * T_ + tp) * HW_ + l;
        for (int c = 0; c < 128; c++) {
            float v = xb[(size_t)c * T_ * HW_];
#pragma unroll
            for (int k = 0; k < 6; k++) acc[k] += y_s[k * 128 + c] * v;
        }
#pragma unroll
        for (int k = 0; k < 6; k++) {
            int tk = tp - offs[k];
            if (tk >= 0 && tk < T_)
                atomicAdd(&g_d[((n * T_ + tk) * 6 + k) * HW_ + l], acc[k]);
        }
    }
}

// ---------------- gate: g = sigmoid(w2[j]*d) - 0.5  (in place) ----------------
__global__ void k_g(const float* __restrict__ w2) {
    int idx = blockIdx.x * blockDim.x + threadIdx.x;
    if (idx >= B_ * 6 * HW_) return;
    int j = (idx / HW_) % 6;
    float a = w2[j] * g_d[idx];
    g_d[idx] = 1.f / (1.f + expf(-a)) - 0.5f;
}

// ---------------- z[n,c,t] += w2[j] * sum_l x[n,c,t+off_j,l] * g[n,t,j,l] ----------------
__global__ void k_z(const float* __restrict__ x, const float* __restrict__ w2) {
    int bid = blockIdx.x;
    int chunk = bid & 3;
    int frame = bid >> 2;
    int n = frame / T_, tp = frame % T_;
    const int offs[6] = {-3, -2, -1, 1, 2, 3};
    __shared__ float gw[6 * HW_];
    int tid = threadIdx.x;
    for (int i = tid; i < 6 * HW_; i += blockDim.x) {
        int k = i / HW_, l = i % HW_;
        int tk = tp - offs[k];
        gw[i] = (tk >= 0 && tk < T_) ? w2[k] * g_d[((n * T_ + tk) * 6 + k) * HW_ + l] : 0.f;
    }
    __syncthreads();
    int warp = tid >> 5, lane = tid & 31;
    for (int ci = 0; ci < 16; ci++) {
        int c = chunk * 128 + warp * 16 + ci;
        const float* row = x + (((size_t)(n * C_ + c)) * T_ + tp) * HW_;
        float acc[6] = {0, 0, 0, 0, 0, 0};
        for (int l = lane; l < HW_; l += 32) {
            float v = row[l];
#pragma unroll
            for (int k = 0; k < 6; k++) acc[k] += gw[k * HW_ + l] * v;
        }
#pragma unroll
        for (int k = 0; k < 6; k++)
            for (int off = 16; off; off >>= 1) acc[k] += __shfl_xor_sync(~0u, acc[k], off);
        if (lane == 0) {
#pragma unroll
            for (int k = 0; k < 6; k++) {
                int tk = tp - offs[k];
                if (tk >= 0 && tk < T_) atomicAdd(&g_z[(n * T_ + tk) * C_ + c], acc[k]);
            }
        }
    }
}

// ---------------- x_down = down_conv_w · x  (smem-tiled, 2 r per thread) ----------------
#define XCH 32
__global__ void k_xdown(const float* __restrict__ x, const float* __restrict__ dw) {
    int rhalf = blockIdx.x & 1;
    int frame = blockIdx.x >> 1;
    int n = frame / T_, t = frame % T_;
    int tid = threadIdx.x;
    int slot = tid >> 5, lane = tid & 31;
    int r0 = rhalf * 16 + slot * 2;
    __shared__ float xs[XCH * HW_];
    float acc0[7] = {0, 0, 0, 0, 0, 0, 0};
    float acc1[7] = {0, 0, 0, 0, 0, 0, 0};
    for (int c0 = 0; c0 < C_; c0 += XCH) {
        __syncthreads();
        for (int i = tid; i < XCH * HW_; i += 256) {
            int c = i / HW_, l = i % HW_;
            xs[i] = x[(((size_t)(n * C_ + c0 + c)) * T_ + t) * HW_ + l];
        }
        __syncthreads();
        for (int c = 0; c < XCH; c++) {
            float w0 = dw[(size_t)r0 * C_ + c0 + c];
            float w1 = dw[(size_t)(r0 + 1) * C_ + c0 + c];
#pragma unroll
            for (int ll = 0; ll < 7; ll++) {
                int li = lane + 32 * ll;
                if (li < HW_) {
                    float v = xs[c * HW_ + li];
                    acc0[ll] += w0 * v;
                    acc1[ll] += w1 * v;
                }
            }
        }
    }
#pragma unroll
    for (int ll = 0; ll < 7; ll++) {
        int li = lane + 32 * ll;
        if (li < HW_) {
            g_xdown[(((size_t)(n * RC_ + r0)) * T_ + t) * HW_ + li]     = acc0[ll];
            g_xdown[(((size_t)(n * RC_ + r0 + 1)) * T_ + t) * HW_ + li] = acc1[ll];
        }
    }
}

// ---------------- fused 3-branch dilated depthwise conv (t-tiled in smem) ----------------
#define DTILE 8
__global__ void k_dw(const float* __restrict__ sa1w, const float* __restrict__ sa1b,
                     const float* __restrict__ sa2w, const float* __restrict__ sa2b,
                     const float* __restrict__ sa3w, const float* __restrict__ sa3b,
                     const float* __restrict__ wts) {
    int bid = bid = blockIdx.x;
    int ttile = bid % (T_ / DTILE);
    int nr = bid / (T_ / DTILE);
    int r = nr % RC_, n = nr / RC_;
    int tstart = ttile * DTILE;
    __shared__ float xs[(DTILE + 8) * HW_];
    __shared__ float ws[3 * 81];
    __shared__ float bsum_s;
    int tid = threadIdx.x;
    if (tid < 81) {
        ws[tid]       = wts[0] * sa1w[r * 81 + tid];
        ws[81 + tid]  = wts[1] * sa2w[r * 81 + tid];
        ws[162 + tid] = wts[2] * sa3w[r * 81 + tid];
    }
    if (tid == 0) bsum_s = wts[0] * sa1b[r] + wts[1] * sa2b[r] + wts[2] * sa3b[r];
    const float* xdbase = g_xdown + ((size_t)(n * RC_ + r)) * T_ * HW_;
    for (int i = tid; i < (DTILE + 8) * HW_; i += blockDim.x) {
        int row = i / HW_, l = i % HW_;
        int tg = tstart - 4 + row;
        xs[i] = (tg >= 0 && tg < T_) ? xdbase[tg * HW_ + l] : 0.f;
    }
    __syncthreads();
    for (int item = tid; item < DTILE * HW_; item += blockDim.x) {
        int tl = item / HW_, l = item % HW_;
        int h = l / 14, w = l % 14;
        float acc = bsum_s;
#pragma unroll
        for (int d = 1; d <= 3; d++) {
            const float* wb = ws + (d - 1) * 81;
            for (int kt = 0; kt < 9; kt++) {
                const float* xrow = xs + (tl + kt) * HW_;
#pragma unroll
                for (int kh = 0; kh < 3; kh++) {
                    int hh = h + (kh - 1) * d;
                    if (hh < 0 || hh >= 14) continue;
#pragma unroll
                    for (int kw = 0; kw < 3; kw++) {
                        int wp = w + (kw - 1) * d;
                        if (wp < 0 || wp >= 14) continue;
                        acc += wb[kt * 9 + kh * 3 + kw] * xrow[hh * 14 + wp];
                    }
                }
            }
        }
        g_aggrc[(((size_t)(n * RC_ + r)) * T_ + tstart + tl) * HW_ + l] = acc;
    }
}

// ---------------- out = feat * (sigmoid(conv_back · agg_rc) - 0.5) ----------------
__global__ void k_out(const float* __restrict__ cbw, float* __restrict__ out) {
    int b = blockIdx.x;
    int n = b / T_, t = b % T_;
    int tid = threadIdx.x;
    int warp = tid >> 5, lane = tid & 31;
    __shared__ float agg_s[RC_ * HW_];
    __shared__ float feat_s[C_];
    feat_s[tid] = g_feat[b * C_ + tid];
    for (int i = tid; i < RC_ * HW_; i += 512) {
        int r = i / HW_, l = i % HW_;
        agg_s[i] = g_aggrc[(((size_t)(n * RC_ + r)) * T_ + t) * HW_ + l];
    }
    __syncthreads();
    for (int ci = 0; ci < 32; ci++) {
        int c = warp * 32 + ci;
        float wreg[RC_];
#pragma unroll
        for (int r = 0; r < RC_; r++) wreg[r] = cbw[(size_t)c * RC_ + r];
        float fc = feat_s[c];
        float* orow = out + (((size_t)(n * C_ + c)) * T_ + t) * HW_;
        for (int l = lane; l < HW_; l += 32) {
            float a = 0.f;
#pragma unroll
            for (int r = 0; r < RC_; r++) a += wreg[r] * agg_s[r * HW_ + l];
            orow[l] = fc * (1.f / (1.f + expf(-a)) - 0.5f);
        }
    }
}

// ---------------- launcher ----------------
extern "C" void kernel_launch(void* const* d_in, const int* in_sizes, int n_in,
                              void* d_out, int out_size) {
    const float* x     = (const float*)d_in[0];
    const float* W2    = (const float*)d_in[1];   // down_conv2_w (C,C)
    const float* dw    = (const float*)d_in[2];   // down_conv_w  (rc,C)
    const float* cbw   = (const float*)d_in[3];   // conv_back_w  (C,rc)
    const float* w2    = (const float*)d_in[4];   // weights2 (6)
    const float* w4    = (const float*)d_in[5];   // weights4 (3)
    const float* wts   = (const float*)d_in[6];   // weights  (3)
    const float* query = (const float*)d_in[7];
    const float* q_w   = (const float*)d_in[8];
    const float* q_b   = (const float*)d_in[9];
    const float* k_w   = (const float*)d_in[10];
    // d_in[11] = k_b (unused: constant shift, softmax-invariant)
    const float* v_w   = (const float*)d_in[12];
    const float* v_b   = (const float*)d_in[13];
    const float* c_w   = (const float*)d_in[14];
    const float* c_b   = (const float*)d_in[15];
    const float* sa1w  = (const float*)d_in[16];
    const float* sa1b  = (const float*)d_in[17];
    const float* sa2w  = (const float*)d_in[18];
    const float* sa2b  = (const float*)d_in[19];
    const float* sa3w  = (const float*)d_in[20];
    const float* sa3b  = (const float*)d_in[21];
    float* out = (float*)d_out;

    float *p_m, *p_tmp1, *p_xatt, *p_z, *p_feat;
    cudaGetSymbolAddress((void**)&p_m, g_m);
    cudaGetSymbolAddress((void**)&p_tmp1, g_tmp1);
    cudaGetSymbolAddress((void**)&p_xatt, g_xatt);
    cudaGetSymbolAddress((void**)&p_z, g_z);
    cudaGetSymbolAddress((void**)&p_feat, g_feat);

    k_zero<<<(B_*6*HW_ + 255) / 256, 256>>>();
    k_prep<<<1, C_>>>(query, q_w, q_b, k_w);
    k_stats<<<B_, 512>>>(x);
    k_rowdot<<<B_, 512>>>(v_w, v_b, p_m, p_tmp1);       // tmp1 = v_w·m + v_b
    k_rowdot<<<B_, 512>>>(c_w, c_b, p_tmp1, p_xatt);    // xatt = c_w·tmp1 + c_b
    k_xq_y<<<B_, 512>>>(w4, W2);                        // y = W2^T · xq
    k_d<<<B_ * 4, 224>>>(x);                            // correlation
    k_g<<<(B_*6*HW_ + 255) / 256, 256>>>(w2);           // sigmoid gate
    k_z<<<B_ * 4, 256>>>(x, w2);                        // gated aggregation
    k_rowdot<<<B_, 512>>>(W2, nullptr, p_z, p_feat);    // feat = W2 · z
    k_xdown<<<B_ * 2, 256>>>(x, dw);
    k_dw<<<NB_ * RC_ * (T_ / DTILE), 256>>>(sa1w, sa1b, sa2w, sa2b, sa3w, sa3b, wts);
    k_out<<<B_, 512>>>(cbw, out);
}